// round 11
// baseline (speedup 1.0000x reference)
#include <cuda_runtime.h>
#include <cuda_bf16.h>
#include <cstdint>

#define D 64
#define KNB 64
#define PADB 72    // bf16 smem row stride in shorts (144B): ldmatrix conflict-free

// ---------------- packed weights in global (prep once) ----------------
__device__ __align__(16) uint4 g_BW2[1024];   // GEMM B frags, lane-consecutive: [(nt*4+ks)*32 + l]
__device__ __align__(16) uint4 g_AW1hi[512];  // hs matvec A frags: [(mi*4+ks)*32+l]
__device__ __align__(16) uint4 g_AW1lo[512];
__device__ __align__(16) uint4 g_AW3hi[512];  // g matvec A frags (W3 = W2^T W1)
__device__ __align__(16) uint4 g_AW3lo[512];
__device__ float g_W3[D * D];                 // fp32 W3 staging
__device__ float g_b3[D];                     // b3 = W2^T b

#define MMA(ac, A, B0, B1) \
    asm volatile("mma.sync.aligned.m16n8k16.row.col.f32.bf16.bf16.f32 " \
        "{%0,%1,%2,%3}, {%4,%5,%6,%7}, {%8,%9}, {%0,%1,%2,%3};" \
        : "+f"((ac)[0]), "+f"((ac)[1]), "+f"((ac)[2]), "+f"((ac)[3]) \
        : "r"((A)[0]), "r"((A)[1]), "r"((A)[2]), "r"((A)[3]), "r"(B0), "r"(B1))

__device__ __forceinline__ uint32_t smem_u32(const void* p) {
    uint32_t a;
    asm("{ .reg .u64 t; cvta.to.shared.u64 t, %1; cvt.u32.u64 %0, t; }" : "=r"(a) : "l"(p));
    return a;
}
__device__ __forceinline__ void ldmat4(unsigned r[4], uint32_t addr) {
    asm volatile("ldmatrix.sync.aligned.m8n8.x4.shared.b16 {%0,%1,%2,%3}, [%4];"
        : "=r"(r[0]), "=r"(r[1]), "=r"(r[2]), "=r"(r[3]) : "r"(addr));
}
__device__ __forceinline__ void split2(float2 f, unsigned& hi, unsigned& lo) {
    unsigned u0 = __float_as_uint(f.x), u1 = __float_as_uint(f.y);
    hi = (u0 >> 16) | (u1 & 0xFFFF0000u);
    float l0 = f.x - __uint_as_float(u0 & 0xFFFF0000u);
    float l1 = f.y - __uint_as_float(u1 & 0xFFFF0000u);
    __nv_bfloat162 p = __floats2bfloat162_rn(l0, l1);
    lo = *reinterpret_cast<unsigned*>(&p);
}
__device__ __forceinline__ void split1(float f, unsigned short& hi, unsigned short& lo) {
    unsigned u = __float_as_uint(f);
    hi = (unsigned short)(u >> 16);
    float lf = f - __uint_as_float(u & 0xFFFF0000u);
    lo = __bfloat16_as_ushort(__float2bfloat16(lf));
}
__device__ __forceinline__ float2 bfrecon(unsigned h, unsigned lo) {
    float2 a = __bfloat1622float2(*reinterpret_cast<__nv_bfloat162*>(&h));
    float2 b = __bfloat1622float2(*reinterpret_cast<__nv_bfloat162*>(&lo));
    return make_float2(a.x + b.x, a.y + b.y);
}

// ---------------- prep kernel 1: B frags, W1 frags, W3 raw, b3 ----------------
__global__ void prep1_kernel(const float* __restrict__ fc_w, const float* __restrict__ fc_b) {
    int idx = blockIdx.x * 256 + threadIdx.x;
    if (idx < 1024) {
        int nt = idx >> 7, ks = (idx >> 5) & 3, g = (idx >> 2) & 7, tg = idx & 3;
        int nn = nt * 8 + g;
        int c0 = ks * 16 + 2 * tg, c1 = c0 + 8;
        const float* Wn = fc_w + nn * 128 + 64;
        unsigned hx, lx, hy, ly;
        split2(make_float2(Wn[c0], Wn[c0 + 1]), hx, lx);
        split2(make_float2(Wn[c1], Wn[c1 + 1]), hy, ly);
        g_BW2[idx] = make_uint4(hx, hy, lx, ly);
    } else if (idx < 1536) {
        int jj = idx - 1024;
        int mi = jj >> 7, ks = (jj >> 5) & 3, l = jj & 31;
        int g = l >> 2, tg = l & 3;
        int ra = mi * 16 + g, rb = ra + 8;
        int c0 = ks * 16 + 2 * tg, c1 = c0 + 8;
        uint4 hi, lo;
        split2(make_float2(fc_w[ra * 128 + c0], fc_w[ra * 128 + c0 + 1]), hi.x, lo.x);
        split2(make_float2(fc_w[rb * 128 + c0], fc_w[rb * 128 + c0 + 1]), hi.y, lo.y);
        split2(make_float2(fc_w[ra * 128 + c1], fc_w[ra * 128 + c1 + 1]), hi.z, lo.z);
        split2(make_float2(fc_w[rb * 128 + c1], fc_w[rb * 128 + c1 + 1]), hi.w, lo.w);
        g_AW1hi[jj] = hi; g_AW1lo[jj] = lo;
    } else if (idx < 1536 + 4096) {
        int j = idx - 1536;
        int f = j >> 6, e = j & 63;
        float s = 0.f;
#pragma unroll 8
        for (int d = 0; d < D; d++)
            s += fc_w[d * 128 + 64 + f] * fc_w[d * 128 + e];
        g_W3[f * 64 + e] = s;
    } else if (idx < 1536 + 4096 + 64) {
        int f = idx - 1536 - 4096;
        float s = 0.f;
#pragma unroll 8
        for (int d = 0; d < D; d++)
            s += fc_w[d * 128 + 64 + f] * fc_b[d];
        g_b3[f] = s;
    }
}

// ---------------- prep kernel 2: pack W3 frags ----------------
__global__ void prep2_kernel() {
    int jj = blockIdx.x * 256 + threadIdx.x;
    if (jj < 512) {
        int mi = jj >> 7, ks = (jj >> 5) & 3, l = jj & 31;
        int g = l >> 2, tg = l & 3;
        int ra = mi * 16 + g, rb = ra + 8;
        int c0 = ks * 16 + 2 * tg, c1 = c0 + 8;
        uint4 hi, lo;
        split2(make_float2(g_W3[ra * 64 + c0], g_W3[ra * 64 + c0 + 1]), hi.x, lo.x);
        split2(make_float2(g_W3[rb * 64 + c0], g_W3[rb * 64 + c0 + 1]), hi.y, lo.y);
        split2(make_float2(g_W3[ra * 64 + c1], g_W3[ra * 64 + c1 + 1]), hi.z, lo.z);
        split2(make_float2(g_W3[rb * 64 + c1], g_W3[rb * 64 + c1 + 1]), hi.w, lo.w);
        g_AW3hi[jj] = hi; g_AW3lo[jj] = lo;
    }
}

// ---------------- main fused kernel: 128 threads, 4 warps ----------------
__global__ void __launch_bounds__(128, 5) kgat_kernel(
    const float* __restrict__ src_embs,
    const float* __restrict__ dst_embs,
    const float* __restrict__ rel_embs,
    const float* __restrict__ fc_b,
    const int*   __restrict__ mask,
    float* __restrict__ out)
{
    __shared__ __align__(16) unsigned short sDhi[D * PADB];
    __shared__ __align__(16) unsigned short sDlo[D * PADB];
    __shared__ __align__(16) unsigned short sRhi[D * PADB];
    __shared__ __align__(16) unsigned short sRlo[D * PADB];
    __shared__ __align__(4) unsigned short sSRChi[D], sSRClo[D];
    __shared__ __align__(4) unsigned short sHShi[D], sHSlo[D];
    __shared__ __align__(4) unsigned short sGhi[D], sGlo[D];
    __shared__ __align__(16) float ssrc[D], shs[D], sb[D];
    __shared__ float sc1[KNB], sc2[KNB], sr2[KNB];
    __shared__ float sdr[KNB], sdh[KNB], satt[KNB];
    __shared__ float sagg[4 * D];
    __shared__ int   smask[KNB];

    const int n = blockIdx.x;
    const int t = threadIdx.x;
    const int w = t >> 5, l = t & 31;
    const int g = l >> 2, tg = l & 3;

    const float* gdst = dst_embs + (size_t)n * (KNB * D);
    const float* grel = rel_embs + (size_t)n * (KNB * D);

    if (t < D) {
        float sv = src_embs[(size_t)n * D + t];
        ssrc[t] = sv;
        split1(sv, sSRChi[t], sSRClo[t]);
        sb[t] = fc_b[t];
        smask[t] = mask[(size_t)n * KNB + t];
    }

    // ---- prologue: split dst/rel into bf16 hi/lo smem ----
    {
        const float4* gd4 = (const float4*)gdst;
        const float4* gr4 = (const float4*)grel;
#pragma unroll
        for (int j = 0; j < 8; j++) {
            int i = t + 128 * j;
            int row = i >> 4, c4 = i & 15;
            float4 dv = gd4[i];
            unsigned h0, l0, h1, l1;
            split2(make_float2(dv.x, dv.y), h0, l0);
            split2(make_float2(dv.z, dv.w), h1, l1);
            *(uint2*)&sDhi[row * PADB + c4 * 4] = make_uint2(h0, h1);
            *(uint2*)&sDlo[row * PADB + c4 * 4] = make_uint2(l0, l1);
            float4 rv = gr4[i];
            split2(make_float2(rv.x, rv.y), h0, l0);
            split2(make_float2(rv.z, rv.w), h1, l1);
            *(uint2*)&sRhi[row * PADB + c4 * 4] = make_uint2(h0, h1);
            *(uint2*)&sRlo[row * PADB + c4 * 4] = make_uint2(l0, l1);
        }
    }
    __syncthreads();

    const uint32_t aDhi = smem_u32(sDhi), aDlo = smem_u32(sDlo);
    const uint32_t aRhi = smem_u32(sRhi), aRlo = smem_u32(sRlo);
    const int m0 = w * 16;
    const uint32_t lmrow = (uint32_t)(m0 + (l & 15)) * (PADB * 2) + (uint32_t)(l >> 4) * 16;

    // ============ GEMM: hd = dst @ W2^T; fused c1/c2/r2 epilogue ============
    {
        float acc[8][4];
#pragma unroll
        for (int i = 0; i < 8; i++)
#pragma unroll
            for (int j = 0; j < 4; j++) acc[i][j] = 0.f;

#pragma unroll
        for (int ks = 0; ks < 4; ks++) {
            unsigned Ahi[4], Alo[4];
            ldmat4(Ahi, aDhi + lmrow + ks * 32);
            ldmat4(Alo, aDlo + lmrow + ks * 32);
#pragma unroll
            for (int nt = 0; nt < 8; nt++) {
                uint4 Bc = g_BW2[((nt * 4 + ks) << 5) + l];
                MMA(acc[nt], Ahi, Bc.x, Bc.y);
                MMA(acc[nt], Alo, Bc.x, Bc.y);
                MMA(acc[nt], Ahi, Bc.z, Bc.w);
            }
        }
        // epilogue: rel fragments via ldmatrix; c1, c2, r2 together
        float c1p0 = 0.f, c1p1 = 0.f, c2p0 = 0.f, c2p1 = 0.f, r2p0 = 0.f, r2p1 = 0.f;
#pragma unroll
        for (int cc = 0; cc < 4; cc++) {
            unsigned Rh[4], Rl[4];
            ldmat4(Rh, aRhi + lmrow + cc * 32);
            ldmat4(Rl, aRlo + lmrow + cc * 32);
            float2 e00 = bfrecon(Rh[0], Rl[0]);
            float2 e01 = bfrecon(Rh[1], Rl[1]);
            float2 e10 = bfrecon(Rh[2], Rl[2]);
            float2 e11 = bfrecon(Rh[3], Rl[3]);
            const int n0 = 2 * cc, n1 = 2 * cc + 1;
            c1p0 += acc[n0][0] * e00.x + acc[n0][1] * e00.y + acc[n1][0] * e10.x + acc[n1][1] * e10.y;
            c1p1 += acc[n0][2] * e01.x + acc[n0][3] * e01.y + acc[n1][2] * e11.x + acc[n1][3] * e11.y;
            c2p0 += acc[n0][0] * acc[n0][0] + acc[n0][1] * acc[n0][1] + acc[n1][0] * acc[n1][0] + acc[n1][1] * acc[n1][1];
            c2p1 += acc[n0][2] * acc[n0][2] + acc[n0][3] * acc[n0][3] + acc[n1][2] * acc[n1][2] + acc[n1][3] * acc[n1][3];
            r2p0 += e00.x * e00.x + e00.y * e00.y + e10.x * e10.x + e10.y * e10.y;
            r2p1 += e01.x * e01.x + e01.y * e01.y + e11.x * e11.x + e11.y * e11.y;
        }
#pragma unroll
        for (int s = 1; s < 4; s <<= 1) {
            c1p0 += __shfl_xor_sync(0xffffffffu, c1p0, s);
            c1p1 += __shfl_xor_sync(0xffffffffu, c1p1, s);
            c2p0 += __shfl_xor_sync(0xffffffffu, c2p0, s);
            c2p1 += __shfl_xor_sync(0xffffffffu, c2p1, s);
            r2p0 += __shfl_xor_sync(0xffffffffu, r2p0, s);
            r2p1 += __shfl_xor_sync(0xffffffffu, r2p1, s);
        }
        if (tg == 0) {
            sc1[m0 + g] = c1p0; sc1[m0 + g + 8] = c1p1;
            sc2[m0 + g] = c2p0; sc2[m0 + g + 8] = c2p1;
            sr2[m0 + g] = r2p0; sr2[m0 + g + 8] = r2p1;
        }
    }
    __syncthreads();

    // ===================== two GAT layers =====================
    for (int layer = 0; layer < 2; layer++) {
        // ---- hs = W1 @ src + b AND g = W3 @ src + b3, one phase, shared B frags ----
        {
            float accH[4] = {0.f, 0.f, 0.f, 0.f};
            float accG[4] = {0.f, 0.f, 0.f, 0.f};
#pragma unroll
            for (int ks = 0; ks < 4; ks++) {
                const int k0 = ks * 16;
                unsigned B0 = 0u, B1 = 0u;
                if (g == 0) {
                    B0 = *(const unsigned*)&sSRChi[k0 + 2 * tg];
                    B1 = *(const unsigned*)&sSRChi[k0 + 2 * tg + 8];
                } else if (g == 1) {
                    B0 = *(const unsigned*)&sSRClo[k0 + 2 * tg];
                    B1 = *(const unsigned*)&sSRClo[k0 + 2 * tg + 8];
                }
                uint4 A1h = g_AW1hi[(w * 4 + ks) * 32 + l];
                uint4 A1l = g_AW1lo[(w * 4 + ks) * 32 + l];
                MMA(accH, ((unsigned*)&A1h), B0, B1);
                MMA(accH, ((unsigned*)&A1l), B0, B1);
                uint4 A3h = g_AW3hi[(w * 4 + ks) * 32 + l];
                uint4 A3l = g_AW3lo[(w * 4 + ks) * 32 + l];
                MMA(accG, ((unsigned*)&A3h), B0, B1);
                MMA(accG, ((unsigned*)&A3l), B0, B1);
            }
            if (tg == 0) {
                float h0 = accH[0] + accH[1] + sb[m0 + g];
                float h1 = accH[2] + accH[3] + sb[m0 + g + 8];
                shs[m0 + g] = h0; shs[m0 + g + 8] = h1;
                split1(h0, sHShi[m0 + g], sHSlo[m0 + g]);
                split1(h1, sHShi[m0 + g + 8], sHSlo[m0 + g + 8]);
                float g0 = accG[0] + accG[1] + g_b3[m0 + g];
                float g1 = accG[2] + accG[3] + g_b3[m0 + g + 8];
                split1(g0, sGhi[m0 + g], sGlo[m0 + g]);
                split1(g1, sGhi[m0 + g + 8], sGlo[m0 + g + 8]);
            }
        }
        __syncthreads();
        // ---- dots via MMA: B cols [hs_hi, hs_lo, g_hi, g_lo]; A = rel (dr), dst (dh) ----
        {
            const unsigned short* vp = (g == 0) ? sHShi : (g == 1) ? sHSlo
                                      : (g == 2) ? sGhi : sGlo;
            float accR[4] = {0.f, 0.f, 0.f, 0.f};
            float accD[4] = {0.f, 0.f, 0.f, 0.f};
#pragma unroll
            for (int ks = 0; ks < 4; ks++) {
                const int k0 = ks * 16;
                unsigned B0 = 0u, B1 = 0u;
                if (g < 4) {
                    B0 = *(const unsigned*)&vp[k0 + 2 * tg];
                    B1 = *(const unsigned*)&vp[k0 + 2 * tg + 8];
                }
                unsigned F[4];
                ldmat4(F, aRhi + lmrow + ks * 32);
                MMA(accR, F, B0, B1);
                ldmat4(F, aRlo + lmrow + ks * 32);
                MMA(accR, F, B0, B1);
                ldmat4(F, aDhi + lmrow + ks * 32);
                MMA(accD, F, B0, B1);
                ldmat4(F, aDlo + lmrow + ks * 32);
                MMA(accD, F, B0, B1);
            }
            if (tg == 0) { sdr[m0 + g] = accR[0] + accR[1]; sdr[m0 + g + 8] = accR[2] + accR[3]; }
            if (tg == 1) { sdh[m0 + g] = accD[0] + accD[1]; sdh[m0 + g + 8] = accD[2] + accD[3]; }
        }
        __syncthreads();
        // ---- logits + masked softmax (warp 0; s2 inline) ----
        if (t < 32) {
            float v = shs[t] * shs[t] + shs[t + 32] * shs[t + 32];
#pragma unroll
            for (int s = 16; s; s >>= 1) v += __shfl_xor_sync(0xffffffffu, v, s);
            const float s2 = v;
            float e[2];
#pragma unroll
            for (int h = 0; h < 2; h++) {
                int k = t + 32 * h;
                float num = sc1[k] + sdr[k];
                float hn2 = s2 + 2.0f * sdh[k] + sc2[k];
                float hn = sqrtf(fmaxf(hn2, 0.0f));
                float rn = sqrtf(sr2[k]);
                float den = fmaxf(hn, 1e-8f) * fmaxf(rn, 1e-8f);
                float ee = num / den;
                ee = (ee < 0.0f) ? 0.2f * ee : ee;
                e[h] = (smask[k] > 0) ? ee : -9e15f;
            }
            float m = fmaxf(e[0], e[1]);
#pragma unroll
            for (int s = 16; s; s >>= 1) m = fmaxf(m, __shfl_xor_sync(0xffffffffu, m, s));
            float x0 = __expf(e[0] - m), x1 = __expf(e[1] - m);
            float sum = x0 + x1;
#pragma unroll
            for (int s = 16; s; s >>= 1) sum += __shfl_xor_sync(0xffffffffu, sum, s);
            float inv = 1.0f / sum;
            satt[t] = x0 * inv; satt[t + 32] = x1 * inv;
        }
        __syncthreads();
        // ---- agg: lane covers col pair (2l, 2l+1), rows 16w..16w+15 from global ----
        {
            float a0 = 0.f, a1 = 0.f;
#pragma unroll
            for (int j = 0; j < 16; j++) {
                const int k = 16 * w + j;
                const float av = satt[k];
                float2 dd = *(const float2*)(gdst + k * 64 + 2 * l);
                a0 = fmaf(av, dd.x, a0);
                a1 = fmaf(av, dd.y, a1);
            }
            *(float2*)&sagg[w * 64 + 2 * l] = make_float2(a0, a1);
        }
        __syncthreads();
        if (t < D) {
            float o = (sagg[t] + sagg[64 + t]) + (sagg[128 + t] + sagg[192 + t]) + ssrc[t];
            if (layer == 0) {
                ssrc[t] = o;
                split1(o, sSRChi[t], sSRClo[t]);
            } else {
                out[(size_t)n * D + t] = o;
            }
        }
        __syncthreads();
    }
}

extern "C" void kernel_launch(void* const* d_in, const int* in_sizes, int n_in,
                              void* d_out, int out_size) {
    const float* src  = (const float*)d_in[0];
    const float* dst  = (const float*)d_in[1];
    const float* rel  = (const float*)d_in[2];
    const float* fcw  = (const float*)d_in[3];
    const float* fcb  = (const float*)d_in[4];
    const int*   mask = (const int*)d_in[5];
    (void)n_in;

    int N = in_sizes[0] / D;   // 50000
    float* outp = (float*)d_out;
    (void)out_size;

    prep1_kernel<<<23, 256>>>(fcw, fcb);
    prep2_kernel<<<2, 256>>>();
    kgat_kernel<<<N, 128>>>(src, dst, rel, fcb, mask, outp);
}